// round 11
// baseline (speedup 1.0000x reference)
#include <cuda_runtime.h>
#include <cstdint>

typedef unsigned long long u64;

#define DIM     512
#define BATCH   2048
#define H1      128
#define H2      64
#define DRUG    2000

// Device-global scratch (no allocation allowed).
__device__ float g_Ptop[DRUG * H1];     // embed[0:2000] @ W1_top + b1
__device__ float g_Pbot[DRUG * H1];     // embed[0:2000] @ W1_bot
__device__ float g_Ptb [BATCH * H1];    // embed[t[b]]   @ W1_bot
__device__ float g_W1T [128 * 1028];    // W1 transposed: [c][k], padded stride 1028
__device__ float g_B2img[8192];         // W2 transposed [c][k], bank-swizzled image

// ---- packed fp32x2 (FFMA2): 2 MACs per issue slot ----
__device__ __forceinline__ u64 fma2(u64 a, u64 b, u64 c) {
    u64 d; asm("fma.rn.f32x2 %0, %1, %2, %3;" : "=l"(d) : "l"(a), "l"(b), "l"(c));
    return d;
}
__device__ __forceinline__ void unpack2(float& lo, float& hi, u64 v) {
    asm("mov.b64 {%0, %1}, %2;" : "=f"(lo), "=f"(hi) : "l"(v));
}

// ---- smem swizzles (rows are 512B; rotate 16B chunks within each 128B line) ----
// A: rotation keyed by row (low 3 bits) -> conflict-free reads AND stores.
__device__ __forceinline__ int swzA(int r, int k4) {   // k4 = k*4 bytes
    return r * 512 + (k4 & 0x180)
         + (((k4 & 0x70) + ((r & 7) << 4)) & 0x70) + (k4 & 0xC);
}
// B: rotation keyed by col-group (c>>2) -> 16 col-groups spread over banks.
__device__ __forceinline__ int swzB(int c, int k4) {
    return c * 512 + (k4 & 0x180)
         + (((k4 & 0x70) + (((c >> 2) & 7) << 4)) & 0x70) + (k4 & 0xC);
}

// ---------------------------------------------------------------------------
// Prep: transpose W1 -> g_W1T ([c][k], stride 1028) and W2 -> swizzled g_B2img.
// ---------------------------------------------------------------------------
__global__ void prep_kernel(const float* __restrict__ W1,
                            const float* __restrict__ W2)
{
    int i = blockIdx.x * 256 + threadIdx.x;
    if (i < 1024 * 128) {                 // W1: (1024, 128) row-major
        int k = i >> 7, c = i & 127;
        g_W1T[c * 1028 + k] = W1[i];
    }
    if (i < 8192) {                       // W2: (128, 64) row-major
        int k = i >> 6, c = i & 63;
        g_B2img[swzB(c, k * 4) >> 2] = W2[i];
    }
}

// ---------------------------------------------------------------------------
// Stage 1 (FFMA2): layer-1 partial products.
// grid.y: 0 = Ptop (W1[:512], +b1), 1 = Pbot, 2 = Ptb (rows = t[b]).
// Block 256: tile 16 rows x 128 cols; thread = 4 rows x 2 cols.
// k-even/odd pairing: A from smem float4 (2 packed u64), W from g_W1T float4.
// ---------------------------------------------------------------------------
__global__ __launch_bounds__(256) void precompute_kernel(
    const float* __restrict__ embed,
    const float* __restrict__ b1,
    const int*   __restrict__ t)
{
    const int job   = blockIdx.y;
    const int nrows = (job == 2) ? BATCH : DRUG;
    const int row0  = blockIdx.x * 16;
    if (row0 >= nrows) return;

    const int k0 = (job == 0) ? 0 : DIM;
    float* out = (job == 0) ? g_Ptop : ((job == 1) ? g_Pbot : g_Ptb);

    __shared__ float sA[16 * 516];       // stride 516 floats (pad vs bank stride)

    const int tid = threadIdx.x;
    for (int idx = tid; idx < 16 * (DIM / 4); idx += 256) {
        int r  = idx >> 7;               // DIM/4 = 128 float4 per row
        int k4 = idx & 127;
        int row = row0 + r;
        int src = 0;
        if (row < nrows) src = (job == 2) ? t[row] : row;
        float4 v = reinterpret_cast<const float4*>(embed + (size_t)src * DIM)[k4];
        reinterpret_cast<float4*>(sA + r * 516)[k4] = v;
    }
    __syncthreads();

    const int cg = tid >> 2;             // 0..63 -> col pair
    const int rg = tid & 3;              // 0..3  -> 4 rows
    const int c  = cg * 2;
    const int r0 = rg * 4;

    const float* w0p = g_W1T + c * 1028 + k0;
    const float* w1p = w0p + 1028;

    u64 acc[4][2];
    #pragma unroll
    for (int i = 0; i < 4; i++) { acc[i][0] = 0ull; acc[i][1] = 0ull; }

    #pragma unroll 4
    for (int k = 0; k < DIM; k += 4) {
        ulonglong2 w0 = *reinterpret_cast<const ulonglong2*>(w0p + k);
        ulonglong2 w1 = *reinterpret_cast<const ulonglong2*>(w1p + k);
        #pragma unroll
        for (int i = 0; i < 4; i++) {
            ulonglong2 a = *reinterpret_cast<const ulonglong2*>(sA + (r0 + i) * 516 + k);
            acc[i][0] = fma2(a.x, w0.x, acc[i][0]);
            acc[i][0] = fma2(a.y, w0.y, acc[i][0]);
            acc[i][1] = fma2(a.x, w1.x, acc[i][1]);
            acc[i][1] = fma2(a.y, w1.y, acc[i][1]);
        }
    }

    const float add0 = (job == 0) ? b1[c]     : 0.f;
    const float add1 = (job == 0) ? b1[c + 1] : 0.f;
    #pragma unroll
    for (int i = 0; i < 4; i++) {
        int row = row0 + r0 + i;
        if (row < nrows) {
            float lo, hi;
            unpack2(lo, hi, acc[i][0]); out[row * H1 + c]     = lo + hi + add0;
            unpack2(lo, hi, acc[i][1]); out[row * H1 + c + 1] = lo + hi + add1;
        }
    }
}

// ---------------------------------------------------------------------------
// Stage 2: register-tiled SGEMM per tile of 128 samples x 64 cols x k=128.
// Block 512 threads: thread tile 4 rows x 4 cols, k-even/odd FFMA2 pairing.
// A (h1 = relu(top+bot)) built in swizzled smem; B copied from swizzled image.
// Epilogue fuses bias+relu+W3 dot and a 16-lane shfl reduction.
// Dynamic smem: A 64KB @0, B 32KB @65536.
// ---------------------------------------------------------------------------
__global__ __launch_bounds__(512) void mlp_tail_kernel(
    const float* __restrict__ b2,
    const float* __restrict__ W3,
    const float* __restrict__ b3,
    const int*   __restrict__ h,
    const int*   __restrict__ n_s,
    float*       __restrict__ out)
{
    extern __shared__ char sm[];
    char* smA = sm;
    char* smB = sm + 65536;

    const int tid  = threadIdx.x;
    const int slot = blockIdx.x >> 4;        // 65 slots x 16 tiles
    const int b0   = (blockIdx.x & 15) * 128;

    // Copy B image (swizzle baked -> raw copy).
    for (int i = tid; i < 2048; i += 512)
        reinterpret_cast<uint4*>(smB)[i] = reinterpret_cast<const uint4*>(g_B2img)[i];

    // Build A: thread handles (row = tid>>2, quarter q = tid&3) = 32 ks.
    {
        const int row = tid >> 2;
        const int q   = tid & 3;
        const int b   = b0 + row;
        const float *tp, *bp;
        if (slot == 0)       { tp = g_Ptop + h[b] * H1;                          bp = g_Ptb  + b * H1; }
        else if (slot <= 32) { tp = g_Ptop + h[b] * H1;                          bp = g_Pbot + n_s[b * 64 + (slot - 1)] * H1; }
        else                 { tp = g_Ptop + n_s[b * 64 + 32 + (slot - 33)] * H1; bp = g_Ptb  + b * H1; }
        const int kb = q * 32;
        #pragma unroll
        for (int j = 0; j < 8; j++) {
            int k = kb + j * 4;
            float4 tv = *reinterpret_cast<const float4*>(tp + k);
            float4 gv = *reinterpret_cast<const float4*>(bp + k);
            float4 hv;
            hv.x = fmaxf(tv.x + gv.x, 0.f);
            hv.y = fmaxf(tv.y + gv.y, 0.f);
            hv.z = fmaxf(tv.z + gv.z, 0.f);
            hv.w = fmaxf(tv.w + gv.w, 0.f);
            *reinterpret_cast<float4*>(smA + swzA(row, k * 4)) = hv;
        }
    }

    // Per-thread epilogue constants (issued before the barrier).
    const int cg = tid & 15;
    const int rg = tid >> 4;
    const int c0 = cg * 4;
    const int r0 = rg * 4;
    const float4 b2v = *reinterpret_cast<const float4*>(b2 + c0);
    const float4 w3v = *reinterpret_cast<const float4*>(W3 + c0);

    __syncthreads();

    // Mainloop: 4x4 thread tile, k-pair FFMA2, all operands pre-packed.
    u64 acc[4][4];
    #pragma unroll
    for (int i = 0; i < 4; i++)
        #pragma unroll
        for (int j = 0; j < 4; j++) acc[i][j] = 0ull;

    #pragma unroll 8
    for (int k = 0; k < H1; k += 4) {
        const int k4 = k * 4;
        ulonglong2 av[4], bv[4];
        #pragma unroll
        for (int i = 0; i < 4; i++)
            av[i] = *reinterpret_cast<const ulonglong2*>(smA + swzA(r0 + i, k4));
        #pragma unroll
        for (int j = 0; j < 4; j++)
            bv[j] = *reinterpret_cast<const ulonglong2*>(smB + swzB(c0 + j, k4));
        #pragma unroll
        for (int i = 0; i < 4; i++)
            #pragma unroll
            for (int j = 0; j < 4; j++) {
                acc[i][j] = fma2(av[i].x, bv[j].x, acc[i][j]);
                acc[i][j] = fma2(av[i].y, bv[j].y, acc[i][j]);
            }
    }

    // Epilogue: bias + relu + W3 dot over this thread's 4 cols, then
    // shfl-reduce over the 16 col-groups (offsets <16 stay in the half-warp).
    const float b2a[4] = {b2v.x, b2v.y, b2v.z, b2v.w};
    const float w3a[4] = {w3v.x, w3v.y, w3v.z, w3v.w};
    float res[4];
    #pragma unroll
    for (int i = 0; i < 4; i++) {
        float s = 0.f;
        #pragma unroll
        for (int j = 0; j < 4; j++) {
            float lo, hi; unpack2(lo, hi, acc[i][j]);
            float v = fmaxf(lo + hi + b2a[j], 0.f);
            s += v * w3a[j];
        }
        res[i] = s;
    }
    #pragma unroll
    for (int off = 1; off < 16; off <<= 1)
        #pragma unroll
        for (int i = 0; i < 4; i++)
            res[i] += __shfl_xor_sync(0xffffffffu, res[i], off);

    if (cg == 0) {
        const float bias = __ldg(b3);
        #pragma unroll
        for (int i = 0; i < 4; i++) {
            int b = b0 + r0 + i;
            int o;
            if (slot == 0)       o = b;
            else if (slot <= 32) o = BATCH + b * 64 + (slot - 1);
            else                 o = BATCH + b * 64 + 32 + (slot - 33);
            out[o] = res[i] + bias;
        }
    }
}

// ---------------------------------------------------------------------------
// Input order: embed, W1, b1, W2, b2, W3, b3, h, t, n_s
// Output: pos (B) then neg (B*64), fp32.
// ---------------------------------------------------------------------------
extern "C" void kernel_launch(void* const* d_in, const int* in_sizes, int n_in,
                              void* d_out, int out_size)
{
    const float* embed = (const float*)d_in[0];
    const float* W1    = (const float*)d_in[1];
    const float* b1    = (const float*)d_in[2];
    const float* W2    = (const float*)d_in[3];
    const float* b2    = (const float*)d_in[4];
    const float* W3    = (const float*)d_in[5];
    const float* b3    = (const float*)d_in[6];
    const int*   h     = (const int*)d_in[7];
    const int*   t     = (const int*)d_in[8];
    const int*   n_s   = (const int*)d_in[9];
    float* out = (float*)d_out;

    prep_kernel<<<512, 256>>>(W1, W2);

    dim3 g1(128, 3);
    precompute_kernel<<<g1, 256>>>(embed, b1, t);

    const int smem_bytes = 65536 + 32768;   // A + B
    cudaFuncSetAttribute(mlp_tail_kernel,
                         cudaFuncAttributeMaxDynamicSharedMemorySize, smem_bytes);
    mlp_tail_kernel<<<65 * 16, 512, smem_bytes>>>(b2, W3, b3, h, n_s, out);
}

// round 13
// speedup vs baseline: 1.0906x; 1.0906x over previous
#include <cuda_runtime.h>
#include <cstdint>

typedef unsigned long long u64;

#define DIM     512
#define BATCH   2048
#define H1      128
#define H2      64
#define DRUG    2000

// Device-global scratch (no allocation allowed).
__device__ float g_Ptop[DRUG * H1];     // embed[0:2000] @ W1_top + b1
__device__ float g_Pbot[DRUG * H1];     // embed[0:2000] @ W1_bot
__device__ float g_Ptb [BATCH * H1];    // embed[t[b]]   @ W1_bot
__device__ float g_B2img[H2 * H1];      // W2^T [c][k], XOR-swizzled smem image

// ---- packed fp32x2 (FFMA2): 2 MACs per issue slot ----
__device__ __forceinline__ u64 fma2(u64 a, u64 b, u64 c) {
    u64 d; asm("fma.rn.f32x2 %0, %1, %2, %3;" : "=l"(d) : "l"(a), "l"(b), "l"(c));
    return d;
}
__device__ __forceinline__ u64 pack2(float lo, float hi) {
    u64 r; asm("mov.b64 %0, {%1, %2};" : "=l"(r) : "f"(lo), "f"(hi)); return r;
}
__device__ __forceinline__ void unpack2(float& lo, float& hi, u64 v) {
    asm("mov.b64 {%0, %1}, %2;" : "=f"(lo), "=f"(hi) : "l"(v));
}

// XOR swizzle for 512-byte rows: permute 16B chunks by (r ^ (r>>3)).
// Rows differing by 8 diverge in bit 0 of the rotation -> distinct banks.
__device__ __forceinline__ int swz(int r, int k4) {
    int rot = (r ^ (r >> 3)) & 31;
    return r * 512 + (k4 & 0xF) + ((((k4 >> 4) ^ rot) & 31) << 4);
}

// ---------------------------------------------------------------------------
// Prep: bake W2^T ([c][k]) into the swizzled smem image (raw-copied by tail).
// ---------------------------------------------------------------------------
__global__ void prep_kernel(const float* __restrict__ W2) {
    int i = blockIdx.x * 256 + threadIdx.x;     // 8192 = 128 k x 64 c
    if (i >= H1 * H2) return;
    int k = i >> 6, c = i & 63;
    g_B2img[swz(c, k * 4) >> 2] = W2[i];
}

// ---------------------------------------------------------------------------
// Stage 1 (FFMA2, k-paired): layer-1 partial products.
// grid.y: 0 = Ptop (W1[:512], +b1), 1 = Pbot, 2 = Ptb (rows = t[b]).
// Block 256: tile 32 rows x 128 cols; thread = 8 rows x 2 cols.
// Weights packed on the fly from row-major W1 (2 packs per 16 FFMA2).
// A reads are warp-uniform (broadcast LDS.64). Dynamic smem: 64 KB.
// ---------------------------------------------------------------------------
__global__ __launch_bounds__(256) void precompute_kernel(
    const float* __restrict__ embed,
    const float* __restrict__ W1,   // (1024, 128) row-major
    const float* __restrict__ b1,
    const int*   __restrict__ t)
{
    const int job   = blockIdx.y;
    const int nrows = (job == 2) ? BATCH : DRUG;
    const int row0  = blockIdx.x * 32;
    if (row0 >= nrows) return;

    const float* W = W1 + ((job == 0) ? 0 : DIM * H1);
    float* out = (job == 0) ? g_Ptop : ((job == 1) ? g_Pbot : g_Ptb);

    extern __shared__ float sA[];        // 32 rows x 512 floats = 64 KB

    const int tid = threadIdx.x;
    for (int idx = tid; idx < 32 * (DIM / 4); idx += 256) {
        int r  = idx >> 7;               // 128 float4 per row
        int k4 = idx & 127;
        int row = row0 + r;
        int src = 0;
        if (row < nrows) src = (job == 2) ? t[row] : row;
        float4 v = reinterpret_cast<const float4*>(embed + (size_t)src * DIM)[k4];
        reinterpret_cast<float4*>(sA + r * 512)[k4] = v;
    }
    __syncthreads();

    const int cg = tid & 63;             // col pair (warp-contiguous -> coalesced W)
    const int rg = tid >> 6;             // 0..3 -> 8 rows each
    const int c  = cg * 2;
    const int r0 = rg * 8;

    u64 acc[8][2];
    #pragma unroll
    for (int i = 0; i < 8; i++) { acc[i][0] = 0ull; acc[i][1] = 0ull; }

    #pragma unroll 4
    for (int k = 0; k < DIM; k += 2) {
        float2 w0 = *reinterpret_cast<const float2*>(W + (k + 0) * H1 + c);
        float2 w1 = *reinterpret_cast<const float2*>(W + (k + 1) * H1 + c);
        u64 px = pack2(w0.x, w1.x);
        u64 py = pack2(w0.y, w1.y);
        #pragma unroll
        for (int i = 0; i < 8; i++) {
            u64 a = *reinterpret_cast<const u64*>(sA + (r0 + i) * 512 + k); // broadcast
            acc[i][0] = fma2(a, px, acc[i][0]);
            acc[i][1] = fma2(a, py, acc[i][1]);
        }
    }

    const float add0 = (job == 0) ? b1[c]     : 0.f;
    const float add1 = (job == 0) ? b1[c + 1] : 0.f;
    #pragma unroll
    for (int i = 0; i < 8; i++) {
        int row = row0 + r0 + i;
        if (row < nrows) {
            float lo, hi;
            unpack2(lo, hi, acc[i][0]); out[row * H1 + c]     = lo + hi + add0;
            unpack2(lo, hi, acc[i][1]); out[row * H1 + c + 1] = lo + hi + add1;
        }
    }
}

// ---------------------------------------------------------------------------
// Stage 2: tile = 128 samples x 64 cols x k=128. Block 256, thread tile 8x4.
// Warp = 2 row-groups x 16 col-groups:
//   av[i]: 2 distinct 16B addrs (bit-0 of rot differs) -> 1 wavefront
//   bv[j]: 16 distinct, uniform 2-way via XOR swizzle   -> 2 wavefronts
// -> 16 LSU cyc vs 64 FFMA2 per k4-iter per warp: FMA-bound.
// Dynamic smem: A 64KB @0 (swizzled), B 32KB @65536 (prebaked image).
// ---------------------------------------------------------------------------
__global__ __launch_bounds__(256) void mlp_tail_kernel(
    const float* __restrict__ b2,
    const float* __restrict__ W3,
    const float* __restrict__ b3,
    const int*   __restrict__ h,
    const int*   __restrict__ n_s,
    float*       __restrict__ out)
{
    extern __shared__ float smf[];
    char* smA = reinterpret_cast<char*>(smf);
    char* smB = reinterpret_cast<char*>(smf) + 65536;

    const int tid  = threadIdx.x;
    const int slot = blockIdx.x >> 4;        // 65 slots x 16 tiles
    const int b0   = (blockIdx.x & 15) * 128;

    // Copy B image (swizzle baked -> raw 32 KB copy).
    for (int i = tid; i < 2048; i += 256)
        reinterpret_cast<uint4*>(smB)[i] = reinterpret_cast<const uint4*>(g_B2img)[i];

    // Build A: thread = (row r = tid>>1, half hh = tid&1) -> 64 k values of
    // h1 = relu(top+bot), stored via the XOR swizzle.
    {
        const int r  = tid >> 1;
        const int hh = tid & 1;
        const int b  = b0 + r;
        const float *tp, *bp;
        if (slot == 0)       { tp = g_Ptop + h[b] * H1;                           bp = g_Ptb  + b * H1; }
        else if (slot <= 32) { tp = g_Ptop + h[b] * H1;                           bp = g_Pbot + n_s[b * 64 + (slot - 1)] * H1; }
        else                 { tp = g_Ptop + n_s[b * 64 + 32 + (slot - 33)] * H1; bp = g_Ptb  + b * H1; }
        const int kb = hh * 64;
        #pragma unroll
        for (int j = 0; j < 16; j++) {
            int k = kb + j * 4;
            float4 tv = *reinterpret_cast<const float4*>(tp + k);
            float4 gv = *reinterpret_cast<const float4*>(bp + k);
            float4 hv;
            hv.x = fmaxf(tv.x + gv.x, 0.f);
            hv.y = fmaxf(tv.y + gv.y, 0.f);
            hv.z = fmaxf(tv.z + gv.z, 0.f);
            hv.w = fmaxf(tv.w + gv.w, 0.f);
            *reinterpret_cast<float4*>(smA + swz(r, k * 4)) = hv;
        }
    }

    // Epilogue constants (issued pre-barrier).
    const int cg = tid & 15;
    const int rg = tid >> 4;
    const int c0 = cg * 4;
    const int r0 = rg * 8;
    const float4 b2v = *reinterpret_cast<const float4*>(b2 + c0);
    const float4 w3v = *reinterpret_cast<const float4*>(W3 + c0);

    __syncthreads();

    // Mainloop: 8x4 thread tile, k-pair FFMA2.
    u64 acc[8][4];
    #pragma unroll
    for (int i = 0; i < 8; i++)
        #pragma unroll
        for (int j = 0; j < 4; j++) acc[i][j] = 0ull;

    #pragma unroll 8
    for (int k = 0; k < H1; k += 4) {
        const int k4 = k * 4;
        ulonglong2 av[8], bv[4];
        #pragma unroll
        for (int i = 0; i < 8; i++)
            av[i] = *reinterpret_cast<const ulonglong2*>(smA + swz(r0 + i, k4));
        #pragma unroll
        for (int j = 0; j < 4; j++)
            bv[j] = *reinterpret_cast<const ulonglong2*>(smB + swz(c0 + j, k4));
        #pragma unroll
        for (int i = 0; i < 8; i++)
            #pragma unroll
            for (int j = 0; j < 4; j++) {
                acc[i][j] = fma2(av[i].x, bv[j].x, acc[i][j]);
                acc[i][j] = fma2(av[i].y, bv[j].y, acc[i][j]);
            }
    }

    // Epilogue: bias + relu + W3 dot, then reduce over 16 col-groups
    // (shfl offsets 1..8 stay within the 16-lane half owning this rg).
    const float b2a[4] = {b2v.x, b2v.y, b2v.z, b2v.w};
    const float w3a[4] = {w3v.x, w3v.y, w3v.z, w3v.w};
    float res[8];
    #pragma unroll
    for (int i = 0; i < 8; i++) {
        float s = 0.f;
        #pragma unroll
        for (int j = 0; j < 4; j++) {
            float lo, hi; unpack2(lo, hi, acc[i][j]);
            float v = fmaxf(lo + hi + b2a[j], 0.f);
            s += v * w3a[j];
        }
        res[i] = s;
    }
    #pragma unroll
    for (int off = 1; off < 16; off <<= 1)
        #pragma unroll
        for (int i = 0; i < 8; i++)
            res[i] += __shfl_xor_sync(0xffffffffu, res[i], off);

    if (cg == 0) {
        const float bias = __ldg(b3);
        #pragma unroll
        for (int i = 0; i < 8; i++) {
            int b = b0 + r0 + i;
            int o;
            if (slot == 0)       o = b;
            else if (slot <= 32) o = BATCH + b * 64 + (slot - 1);
            else                 o = BATCH + b * 64 + 32 + (slot - 33);
            out[o] = res[i] + bias;
        }
    }
}

// ---------------------------------------------------------------------------
// Input order: embed, W1, b1, W2, b2, W3, b3, h, t, n_s
// Output: pos (B) then neg (B*64), fp32.
// ---------------------------------------------------------------------------
extern "C" void kernel_launch(void* const* d_in, const int* in_sizes, int n_in,
                              void* d_out, int out_size)
{
    const float* embed = (const float*)d_in[0];
    const float* W1    = (const float*)d_in[1];
    const float* b1    = (const float*)d_in[2];
    const float* W2    = (const float*)d_in[3];
    const float* b2    = (const float*)d_in[4];
    const float* W3    = (const float*)d_in[5];
    const float* b3    = (const float*)d_in[6];
    const int*   h     = (const int*)d_in[7];
    const int*   t     = (const int*)d_in[8];
    const int*   n_s   = (const int*)d_in[9];
    float* out = (float*)d_out;

    prep_kernel<<<32, 256>>>(W2);

    cudaFuncSetAttribute(precompute_kernel,
                         cudaFuncAttributeMaxDynamicSharedMemorySize, 65536);
    dim3 g1(64, 3);
    precompute_kernel<<<g1, 256, 65536>>>(embed, W1, b1, t);

    const int smem_bytes = 65536 + 32768;   // A + B
    cudaFuncSetAttribute(mlp_tail_kernel,
                         cudaFuncAttributeMaxDynamicSharedMemorySize, smem_bytes);
    mlp_tail_kernel<<<65 * 16, 256, smem_bytes>>>(b2, W3, b3, h, n_s, out);
}